// round 2
// baseline (speedup 1.0000x reference)
#include <cuda_runtime.h>

#define B_ 4
#define T_ 4096
#define C_ 1024
#define H_ 64

#define NEG_BIG (-1e30f)

// Scratch for projected Q, K, V: [B, T, H] fp32, 4 MB each.
__device__ float g_Q[B_ * T_ * H_];
__device__ float g_K[B_ * T_ * H_];
__device__ float g_V[B_ * T_ * H_];

// ---------------------------------------------------------------------------
// Kernel 1: QKV projections.  dst[bt, h] = sum_c x[bt, c] * W[h, c]
// Grid: (T*B/64, 3). Block: 256 threads. 64x64 output tile per block,
// k-chunks of 32, 4x4 register microtiles, transposed smem for float4 loads.
// ---------------------------------------------------------------------------
__global__ __launch_bounds__(256)
void proj_kernel(const float* __restrict__ x,
                 const float* __restrict__ Wq,
                 const float* __restrict__ Wk,
                 const float* __restrict__ Wv) {
    __shared__ float x_s[32][64];   // [k][row]
    __shared__ float w_s[32][64];   // [k][h]

    const float* W;
    float* dst;
    if (blockIdx.y == 0)      { W = Wq; dst = g_Q; }
    else if (blockIdx.y == 1) { W = Wk; dst = g_K; }
    else                      { W = Wv; dst = g_V; }

    const int row0 = blockIdx.x * 64;
    const int t  = threadIdx.x;
    const int tx = t & 15;          // 16 threads -> rows
    const int ty = t >> 4;          // 16 threads -> cols
    const int lr = t >> 2;          // load row 0..63
    const int lk = (t & 3) * 8;     // load k offset (8 floats)

    float acc[4][4] = {};

    for (int kc = 0; kc < C_; kc += 32) {
        const float4 xa = *(const float4*)(x + (size_t)(row0 + lr) * C_ + kc + lk);
        const float4 xb = *(const float4*)(x + (size_t)(row0 + lr) * C_ + kc + lk + 4);
        x_s[lk + 0][lr] = xa.x; x_s[lk + 1][lr] = xa.y;
        x_s[lk + 2][lr] = xa.z; x_s[lk + 3][lr] = xa.w;
        x_s[lk + 4][lr] = xb.x; x_s[lk + 5][lr] = xb.y;
        x_s[lk + 6][lr] = xb.z; x_s[lk + 7][lr] = xb.w;

        const float4 wa = *(const float4*)(W + (size_t)lr * C_ + kc + lk);
        const float4 wb = *(const float4*)(W + (size_t)lr * C_ + kc + lk + 4);
        w_s[lk + 0][lr] = wa.x; w_s[lk + 1][lr] = wa.y;
        w_s[lk + 2][lr] = wa.z; w_s[lk + 3][lr] = wa.w;
        w_s[lk + 4][lr] = wb.x; w_s[lk + 5][lr] = wb.y;
        w_s[lk + 6][lr] = wb.z; w_s[lk + 7][lr] = wb.w;

        __syncthreads();

        #pragma unroll
        for (int k = 0; k < 32; k++) {
            const float4 a = *(const float4*)&x_s[k][tx * 4];
            const float4 b = *(const float4*)&w_s[k][ty * 4];
            acc[0][0] += a.x * b.x; acc[0][1] += a.x * b.y;
            acc[0][2] += a.x * b.z; acc[0][3] += a.x * b.w;
            acc[1][0] += a.y * b.x; acc[1][1] += a.y * b.y;
            acc[1][2] += a.y * b.z; acc[1][3] += a.y * b.w;
            acc[2][0] += a.z * b.x; acc[2][1] += a.z * b.y;
            acc[2][2] += a.z * b.z; acc[2][3] += a.z * b.w;
            acc[3][0] += a.w * b.x; acc[3][1] += a.w * b.y;
            acc[3][2] += a.w * b.z; acc[3][3] += a.w * b.w;
        }
        __syncthreads();
    }

    #pragma unroll
    for (int i = 0; i < 4; i++)
        #pragma unroll
        for (int j = 0; j < 4; j++)
            dst[(size_t)(row0 + tx * 4 + i) * H_ + ty * 4 + j] = acc[i][j];
}

// ---------------------------------------------------------------------------
// Kernel 2: flash attention with shifted causal mask (j <= i+1) and double
// scaling (exponent = qk / 64). Grid: (T/64, B). Block: 256 threads.
// smem layouts: q_s[h][r], k_s[h][j], v_s[j][c], p_s[j][r] (all stride 64,
// float4-aligned, conflict-free for the 4x4 microtile operand loads).
// ---------------------------------------------------------------------------
__global__ __launch_bounds__(256)
void attn_kernel(float* __restrict__ out) {
    extern __shared__ float sm[];
    float* q_s = sm;                 // [64][64]  (h, r)
    float* k_s = sm + 4096;         // [64][64]  (h, j)
    float* v_s = sm + 8192;         // [64][64]  (j, c)
    float* p_s = sm + 12288;        // [64][64]  (j, r)
    float* f_s = sm + 16384;        // [64] row rescale factors
    float* l_s = f_s + 64;          // [64] final row sums

    const int qb = blockIdx.x;
    const int b  = blockIdx.y;
    const int t  = threadIdx.x;
    const int tx = t & 15;           // rows (r0 = 4*tx)
    const int ty = t >> 4;           // cols (c0/j0 = 4*ty)
    const int lr = t >> 2;           // load row 0..63
    const int lh = (t & 3) * 16;     // load col offset (16 floats)

    const size_t base = (size_t)b * T_ * H_;

    // Load Q tile transposed: q_s[h][r]
    {
        const float* src = g_Q + base + (size_t)(qb * 64 + lr) * H_ + lh;
        #pragma unroll
        for (int u = 0; u < 4; u++) {
            const float4 v = *(const float4*)(src + u * 4);
            q_s[(lh + u * 4 + 0) * 64 + lr] = v.x;
            q_s[(lh + u * 4 + 1) * 64 + lr] = v.y;
            q_s[(lh + u * 4 + 2) * 64 + lr] = v.z;
            q_s[(lh + u * 4 + 3) * 64 + lr] = v.w;
        }
    }

    float o[4][4] = {};
    float m_reg = NEG_BIG;   // running max (only meaningful for t < 64)
    float l_reg = 0.0f;      // running sum

    const int kb_max = min(qb + 1, T_ / 64 - 1);

    for (int kb = 0; kb <= kb_max; kb++) {
        // Load K tile transposed: k_s[h][j]
        {
            const float* src = g_K + base + (size_t)(kb * 64 + lr) * H_ + lh;
            #pragma unroll
            for (int u = 0; u < 4; u++) {
                const float4 v = *(const float4*)(src + u * 4);
                k_s[(lh + u * 4 + 0) * 64 + lr] = v.x;
                k_s[(lh + u * 4 + 1) * 64 + lr] = v.y;
                k_s[(lh + u * 4 + 2) * 64 + lr] = v.z;
                k_s[(lh + u * 4 + 3) * 64 + lr] = v.w;
            }
        }
        // Load V tile natural: v_s[j][c]
        {
            const float* src = g_V + base + (size_t)(kb * 64 + lr) * H_ + lh;
            #pragma unroll
            for (int u = 0; u < 4; u++)
                *(float4*)(v_s + lr * 64 + lh + u * 4) = *(const float4*)(src + u * 4);
        }
        __syncthreads();

        // Scores s[r][j] = sum_h q[r][h] * k[j][h]
        float s[4][4] = {};
        #pragma unroll 8
        for (int h = 0; h < 64; h++) {
            const float4 a = *(const float4*)(q_s + h * 64 + tx * 4);
            const float4 b4 = *(const float4*)(k_s + h * 64 + ty * 4);
            s[0][0] += a.x * b4.x; s[0][1] += a.x * b4.y;
            s[0][2] += a.x * b4.z; s[0][3] += a.x * b4.w;
            s[1][0] += a.y * b4.x; s[1][1] += a.y * b4.y;
            s[1][2] += a.y * b4.z; s[1][3] += a.y * b4.w;
            s[2][0] += a.z * b4.x; s[2][1] += a.z * b4.y;
            s[2][2] += a.z * b4.z; s[2][3] += a.z * b4.w;
            s[3][0] += a.w * b4.x; s[3][1] += a.w * b4.y;
            s[3][2] += a.w * b4.z; s[3][3] += a.w * b4.w;
        }

        // Scale (double-scaled softmax: qk/64), mask (j <= i+1), write p_s[j][r]
        const float sc2 = 1.0f / 64.0f;
        #pragma unroll
        for (int i = 0; i < 4; i++) {
            const int gi = qb * 64 + tx * 4 + i;
            #pragma unroll
            for (int j = 0; j < 4; j++) {
                const int gj = kb * 64 + ty * 4 + j;
                const float val = (gj <= gi + 1) ? s[i][j] * sc2 : NEG_BIG;
                p_s[(ty * 4 + j) * 64 + (tx * 4 + i)] = val;
            }
        }
        __syncthreads();

        // Online softmax stats: thread r (< 64) owns row r; column reads of
        // p_s[j][r] are conflict-free (bank = r % 32, distinct per lane).
        if (t < 64) {
            float vmax = NEG_BIG;
            #pragma unroll 8
            for (int j = 0; j < 64; j++)
                vmax = fmaxf(vmax, p_s[j * 64 + t]);
            const float m_new = fmaxf(m_reg, vmax);
            const float fac = __expf(m_reg - m_new);
            float ssum = 0.0f;
            #pragma unroll 8
            for (int j = 0; j < 64; j++) {
                const float e = __expf(p_s[j * 64 + t] - m_new);
                p_s[j * 64 + t] = e;
                ssum += e;
            }
            l_reg = l_reg * fac + ssum;
            m_reg = m_new;
            f_s[t] = fac;
        }
        __syncthreads();

        // Rescale accumulators and accumulate P @ V
        float f[4];
        #pragma unroll
        for (int i = 0; i < 4; i++) f[i] = f_s[tx * 4 + i];
        #pragma unroll
        for (int i = 0; i < 4; i++)
            #pragma unroll
            for (int j = 0; j < 4; j++) o[i][j] *= f[i];

        #pragma unroll 8
        for (int jj = 0; jj < 64; jj++) {
            const float4 a = *(const float4*)(p_s + jj * 64 + tx * 4);
            const float4 b4 = *(const float4*)(v_s + jj * 64 + ty * 4);
            o[0][0] += a.x * b4.x; o[0][1] += a.x * b4.y;
            o[0][2] += a.x * b4.z; o[0][3] += a.x * b4.w;
            o[1][0] += a.y * b4.x; o[1][1] += a.y * b4.y;
            o[1][2] += a.y * b4.z; o[1][3] += a.y * b4.w;
            o[2][0] += a.z * b4.x; o[2][1] += a.z * b4.y;
            o[2][2] += a.z * b4.z; o[2][3] += a.z * b4.w;
            o[3][0] += a.w * b4.x; o[3][1] += a.w * b4.y;
            o[3][2] += a.w * b4.z; o[3][3] += a.w * b4.w;
        }
        __syncthreads();
    }

    if (t < 64) l_s[t] = l_reg;
    __syncthreads();

    #pragma unroll
    for (int i = 0; i < 4; i++) {
        const float inv = 1.0f / l_s[tx * 4 + i];
        #pragma unroll
        for (int j = 0; j < 4; j++)
            out[base + (size_t)(qb * 64 + tx * 4 + i) * H_ + ty * 4 + j] =
                o[i][j] * inv;
    }
}

// ---------------------------------------------------------------------------
// Launch
// ---------------------------------------------------------------------------
extern "C" void kernel_launch(void* const* d_in, const int* in_sizes, int n_in,
                              void* d_out, int out_size) {
    const float* x  = (const float*)d_in[0];
    const float* Wk = (const float*)d_in[1];
    const float* Wq = (const float*)d_in[2];
    const float* Wv = (const float*)d_in[3];
    float* out = (float*)d_out;

    const int attn_smem = (4 * 64 * 64 + 2 * 64) * (int)sizeof(float); // 66048 B
    cudaFuncSetAttribute(attn_kernel,
                         cudaFuncAttributeMaxDynamicSharedMemorySize, attn_smem);

    proj_kernel<<<dim3((B_ * T_) / 64, 3), 256>>>(x, Wq, Wk, Wv);
    attn_kernel<<<dim3(T_ / 64, B_), 256, attn_smem>>>(out);
}

// round 3
// speedup vs baseline: 1.3664x; 1.3664x over previous
#include <cuda_runtime.h>

#define B_ 4
#define T_ 4096
#define C_ 1024
#define H_ 64
#define SPLITS 4

#define NEG_BIG (-1e30f)

// Scratch: projected Q, K, V [B,T,H] fp32 (4 MB each).
__device__ float g_Q[B_ * T_ * H_];
__device__ float g_K[B_ * T_ * H_];
__device__ float g_V[B_ * T_ * H_];
// Split-K partials: unnormalized O, running max m, running sum l per split.
__device__ float g_opart[SPLITS][B_ * T_ * H_];
__device__ float g_m[SPLITS][B_ * T_];
__device__ float g_l[SPLITS][B_ * T_];

// ---------------- packed f32x2 helpers (B300 dual-fp32 pipe) ----------------
__device__ __forceinline__ unsigned long long pk2(float lo, float hi) {
    unsigned long long r;
    asm("mov.b64 %0, {%1, %2};" : "=l"(r) : "f"(lo), "f"(hi));
    return r;
}
__device__ __forceinline__ float2 upk(unsigned long long v) {
    float2 r;
    asm("mov.b64 {%0, %1}, %2;" : "=f"(r.x), "=f"(r.y) : "l"(v));
    return r;
}
__device__ __forceinline__ void ffma2(unsigned long long& d,
                                      unsigned long long a,
                                      unsigned long long b) {
    asm("fma.rn.f32x2 %0, %1, %2, %0;" : "+l"(d) : "l"(a), "l"(b));
}
__device__ __forceinline__ void fmul2(unsigned long long& d,
                                      unsigned long long a) {
    asm("mul.rn.f32x2 %0, %0, %1;" : "+l"(d) : "l"(a));
}

// ---------------------------------------------------------------------------
// Kernel 1: QKV projections (unchanged — near fp32 floor already).
// ---------------------------------------------------------------------------
__global__ __launch_bounds__(256)
void proj_kernel(const float* __restrict__ x,
                 const float* __restrict__ Wq,
                 const float* __restrict__ Wk,
                 const float* __restrict__ Wv) {
    __shared__ float x_s[32][64];
    __shared__ float w_s[32][64];

    const float* W;
    float* dst;
    if (blockIdx.y == 0)      { W = Wq; dst = g_Q; }
    else if (blockIdx.y == 1) { W = Wk; dst = g_K; }
    else                      { W = Wv; dst = g_V; }

    const int row0 = blockIdx.x * 64;
    const int t  = threadIdx.x;
    const int tx = t & 15;
    const int ty = t >> 4;
    const int lr = t >> 2;
    const int lk = (t & 3) * 8;

    float acc[4][4] = {};

    for (int kc = 0; kc < C_; kc += 32) {
        const float4 xa = *(const float4*)(x + (size_t)(row0 + lr) * C_ + kc + lk);
        const float4 xb = *(const float4*)(x + (size_t)(row0 + lr) * C_ + kc + lk + 4);
        x_s[lk + 0][lr] = xa.x; x_s[lk + 1][lr] = xa.y;
        x_s[lk + 2][lr] = xa.z; x_s[lk + 3][lr] = xa.w;
        x_s[lk + 4][lr] = xb.x; x_s[lk + 5][lr] = xb.y;
        x_s[lk + 6][lr] = xb.z; x_s[lk + 7][lr] = xb.w;

        const float4 wa = *(const float4*)(W + (size_t)lr * C_ + kc + lk);
        const float4 wb = *(const float4*)(W + (size_t)lr * C_ + kc + lk + 4);
        w_s[lk + 0][lr] = wa.x; w_s[lk + 1][lr] = wa.y;
        w_s[lk + 2][lr] = wa.z; w_s[lk + 3][lr] = wa.w;
        w_s[lk + 4][lr] = wb.x; w_s[lk + 5][lr] = wb.y;
        w_s[lk + 6][lr] = wb.z; w_s[lk + 7][lr] = wb.w;

        __syncthreads();

        #pragma unroll
        for (int k = 0; k < 32; k++) {
            const float4 a = *(const float4*)&x_s[k][tx * 4];
            const float4 b = *(const float4*)&w_s[k][ty * 4];
            acc[0][0] += a.x * b.x; acc[0][1] += a.x * b.y;
            acc[0][2] += a.x * b.z; acc[0][3] += a.x * b.w;
            acc[1][0] += a.y * b.x; acc[1][1] += a.y * b.y;
            acc[1][2] += a.y * b.z; acc[1][3] += a.y * b.w;
            acc[2][0] += a.z * b.x; acc[2][1] += a.z * b.y;
            acc[2][2] += a.z * b.z; acc[2][3] += a.z * b.w;
            acc[3][0] += a.w * b.x; acc[3][1] += a.w * b.y;
            acc[3][2] += a.w * b.z; acc[3][3] += a.w * b.w;
        }
        __syncthreads();
    }

    #pragma unroll
    for (int i = 0; i < 4; i++)
        #pragma unroll
        for (int j = 0; j < 4; j++)
            dst[(size_t)(row0 + tx * 4 + i) * H_ + ty * 4 + j] = acc[i][j];
}

// ---------------------------------------------------------------------------
// Kernel 2: split-K flash attention.
// Grid (qb=64, split=4, b=4). Block 256 = 16x16 threads, 4x4 microtiles.
// Each split handles kb in {split, split+4, ...} and writes unnormalized
// partial (O, m, l). Softmax stats live in registers (shfl_xor over the
// 16-lane column groups). GEMMs use packed fma.rn.f32x2.
// smem: q_s[h][r] (4K f), kp_s (K xor-swizzled, then P row-major; 4K f),
// v_s[j][c] (4K f) = 48 KB.
// ---------------------------------------------------------------------------
__global__ __launch_bounds__(256)
void attn_split_kernel() {
    extern __shared__ float sm[];
    float* q_s  = sm;           // [64][64] (h, r)
    float* kp_s = sm + 4096;    // K swizzled [h][j-quads], later P [r][j]
    float* v_s  = sm + 8192;    // [64][64] (j, c)

    const int qb = blockIdx.x;
    const int sp = blockIdx.y;
    const int b  = blockIdx.z;
    const int t  = threadIdx.x;
    const int tx = t >> 4;          // row group: rows tx*4 .. tx*4+3
    const int ty = t & 15;          // col group: cols ty*4 .. ty*4+3
    const int lr = t >> 2;          // loader row 0..63
    const int lh = (t & 3) * 16;    // loader col offset

    const size_t base = (size_t)b * T_ * H_;

    // Load Q transposed once: q_s[h][r]
    {
        const float* src = g_Q + base + (size_t)(qb * 64 + lr) * H_ + lh;
        #pragma unroll
        for (int u = 0; u < 4; u++) {
            const float4 v = *(const float4*)(src + u * 4);
            q_s[(lh + u * 4 + 0) * 64 + lr] = v.x;
            q_s[(lh + u * 4 + 1) * 64 + lr] = v.y;
            q_s[(lh + u * 4 + 2) * 64 + lr] = v.z;
            q_s[(lh + u * 4 + 3) * 64 + lr] = v.w;
        }
    }

    unsigned long long o2[4][2] = {};            // packed fp32 pairs
    float m[4], l[4];
    #pragma unroll
    for (int i = 0; i < 4; i++) { m[i] = NEG_BIG; l[i] = 0.0f; }

    const int kb_max = min(qb + 1, T_ / 64 - 1);
    const float sc2 = 1.0f / 64.0f;

    for (int kb = sp; kb <= kb_max; kb += SPLITS) {
        // --- load K (xor-swizzled transpose) and V (natural) ---
        {
            const float* ksrc = g_K + base + (size_t)(kb * 64 + lr) * H_ + lh;
            const float* vsrc = g_V + base + (size_t)(kb * 64 + lr) * H_ + lh;
            #pragma unroll
            for (int u = 0; u < 4; u++) {
                const float4 kv = *(const float4*)(ksrc + u * 4);
                const int h0 = lh + u * 4;
                const int jq = lr >> 2, jw = lr & 3;
                kp_s[(h0 + 0) * 64 + ((jq ^ ((h0 + 0) & 15)) << 2) + jw] = kv.x;
                kp_s[(h0 + 1) * 64 + ((jq ^ ((h0 + 1) & 15)) << 2) + jw] = kv.y;
                kp_s[(h0 + 2) * 64 + ((jq ^ ((h0 + 2) & 15)) << 2) + jw] = kv.z;
                kp_s[(h0 + 3) * 64 + ((jq ^ ((h0 + 3) & 15)) << 2) + jw] = kv.w;
                *(float4*)(v_s + lr * 64 + h0) = *(const float4*)(vsrc + u * 4);
            }
        }
        __syncthreads();

        // --- S = Q K^T (packed f32x2, accumulators paired along j) ---
        unsigned long long s2[4][2] = {};
        #pragma unroll 4
        for (int h = 0; h < 64; h++) {
            const float4 qf = *(const float4*)(q_s + h * 64 + tx * 4);
            const ulonglong2 kk = *(const ulonglong2*)
                (kp_s + h * 64 + ((ty ^ (h & 15)) << 2));
            const unsigned long long q0 = pk2(qf.x, qf.x);
            const unsigned long long q1 = pk2(qf.y, qf.y);
            const unsigned long long q2 = pk2(qf.z, qf.z);
            const unsigned long long q3 = pk2(qf.w, qf.w);
            ffma2(s2[0][0], q0, kk.x); ffma2(s2[0][1], q0, kk.y);
            ffma2(s2[1][0], q1, kk.x); ffma2(s2[1][1], q1, kk.y);
            ffma2(s2[2][0], q2, kk.x); ffma2(s2[2][1], q2, kk.y);
            ffma2(s2[3][0], q3, kk.x); ffma2(s2[3][1], q3, kk.y);
        }
        __syncthreads();   // kp_s reads done; safe to overwrite with P

        // --- mask + online softmax in registers ---
        float e[4][4], fac[4];
        #pragma unroll
        for (int i = 0; i < 4; i++) {
            const float2 pa = upk(s2[i][0]);
            const float2 pb = upk(s2[i][1]);
            float sv[4] = { pa.x, pa.y, pb.x, pb.y };
            const int gi = qb * 64 + tx * 4 + i;
            bool al[4];
            float rm = NEG_BIG;
            #pragma unroll
            for (int j = 0; j < 4; j++) {
                const int gj = kb * 64 + ty * 4 + j;
                al[j] = (gj <= gi + 1);
                sv[j] = al[j] ? sv[j] * sc2 : NEG_BIG;
                rm = fmaxf(rm, sv[j]);
            }
            rm = fmaxf(rm, __shfl_xor_sync(0xffffffffu, rm, 1, 16));
            rm = fmaxf(rm, __shfl_xor_sync(0xffffffffu, rm, 2, 16));
            rm = fmaxf(rm, __shfl_xor_sync(0xffffffffu, rm, 4, 16));
            rm = fmaxf(rm, __shfl_xor_sync(0xffffffffu, rm, 8, 16));
            const float mn = fmaxf(m[i], rm);
            fac[i] = __expf(m[i] - mn);
            float rs = 0.0f;
            #pragma unroll
            for (int j = 0; j < 4; j++) {
                const float ev = al[j] ? __expf(sv[j] - mn) : 0.0f;
                e[i][j] = ev;
                rs += ev;
            }
            rs += __shfl_xor_sync(0xffffffffu, rs, 1, 16);
            rs += __shfl_xor_sync(0xffffffffu, rs, 2, 16);
            rs += __shfl_xor_sync(0xffffffffu, rs, 4, 16);
            rs += __shfl_xor_sync(0xffffffffu, rs, 8, 16);
            l[i] = l[i] * fac[i] + rs;
            m[i] = mn;
        }

        // rescale accumulators
        #pragma unroll
        for (int i = 0; i < 4; i++) {
            const unsigned long long f2 = pk2(fac[i], fac[i]);
            fmul2(o2[i][0], f2);
            fmul2(o2[i][1], f2);
        }

        // store P row-major: p[r][j]
        #pragma unroll
        for (int i = 0; i < 4; i++) {
            float4 pv;
            pv.x = e[i][0]; pv.y = e[i][1]; pv.z = e[i][2]; pv.w = e[i][3];
            *(float4*)(kp_s + (tx * 4 + i) * 64 + ty * 4) = pv;
        }
        __syncthreads();   // P visible

        // --- O += P V (packed f32x2) ---
        #pragma unroll 2
        for (int jc = 0; jc < 16; jc++) {
            float pa[4][4];
            #pragma unroll
            for (int i = 0; i < 4; i++)
                *(float4*)pa[i] = *(const float4*)(kp_s + (tx * 4 + i) * 64 + jc * 4);
            ulonglong2 vb[4];
            #pragma unroll
            for (int u = 0; u < 4; u++)
                vb[u] = *(const ulonglong2*)(v_s + (jc * 4 + u) * 64 + ty * 4);
            #pragma unroll
            for (int u = 0; u < 4; u++) {
                #pragma unroll
                for (int i = 0; i < 4; i++) {
                    const unsigned long long pd = pk2(pa[i][u], pa[i][u]);
                    ffma2(o2[i][0], pd, vb[u].x);
                    ffma2(o2[i][1], pd, vb[u].y);
                }
            }
        }
        __syncthreads();   // v_s / kp_s consumed; safe for next-iter loads
    }

    // --- write partials ---
    const size_t rb = (size_t)b * T_ + qb * 64;
    #pragma unroll
    for (int i = 0; i < 4; i++) {
        const float2 a = upk(o2[i][0]);
        const float2 c = upk(o2[i][1]);
        float4 ov; ov.x = a.x; ov.y = a.y; ov.z = c.x; ov.w = c.y;
        *(float4*)(g_opart[sp] + (rb + tx * 4 + i) * 64 + ty * 4) = ov;
    }
    if (ty == 0) {
        #pragma unroll
        for (int i = 0; i < 4; i++) {
            g_m[sp][rb + tx * 4 + i] = m[i];
            g_l[sp][rb + tx * 4 + i] = l[i];
        }
    }
}

// ---------------------------------------------------------------------------
// Kernel 3: combine split partials.  out = sum_s(w_s * O_s) / sum_s(w_s * l_s)
// Grid 1024, block 256 = 16 rows x 16 col-quads.
// ---------------------------------------------------------------------------
__global__ __launch_bounds__(256)
void combine_kernel(float* __restrict__ out) {
    const int t = threadIdx.x;
    const size_t r = (size_t)blockIdx.x * 16 + (t >> 4);
    const int c = (t & 15) * 4;

    float mv[SPLITS], lv[SPLITS];
    float M = NEG_BIG;
    #pragma unroll
    for (int s = 0; s < SPLITS; s++) {
        mv[s] = g_m[s][r];
        lv[s] = g_l[s][r];
        M = fmaxf(M, mv[s]);
    }
    float w[SPLITS], L = 0.0f;
    #pragma unroll
    for (int s = 0; s < SPLITS; s++) {
        w[s] = __expf(mv[s] - M);
        L += lv[s] * w[s];
    }
    float4 acc = make_float4(0.f, 0.f, 0.f, 0.f);
    #pragma unroll
    for (int s = 0; s < SPLITS; s++) {
        const float4 o = *(const float4*)(g_opart[s] + r * 64 + c);
        acc.x += w[s] * o.x; acc.y += w[s] * o.y;
        acc.z += w[s] * o.z; acc.w += w[s] * o.w;
    }
    const float inv = 1.0f / L;
    float4 ov;
    ov.x = acc.x * inv; ov.y = acc.y * inv;
    ov.z = acc.z * inv; ov.w = acc.w * inv;
    *(float4*)(out + r * 64 + c) = ov;
}

// ---------------------------------------------------------------------------
// Launch
// ---------------------------------------------------------------------------
extern "C" void kernel_launch(void* const* d_in, const int* in_sizes, int n_in,
                              void* d_out, int out_size) {
    const float* x  = (const float*)d_in[0];
    const float* Wk = (const float*)d_in[1];
    const float* Wq = (const float*)d_in[2];
    const float* Wv = (const float*)d_in[3];
    float* out = (float*)d_out;

    const int attn_smem = 3 * 64 * 64 * (int)sizeof(float); // 49152 B
    cudaFuncSetAttribute(attn_split_kernel,
                         cudaFuncAttributeMaxDynamicSharedMemorySize, attn_smem);

    proj_kernel<<<dim3((B_ * T_) / 64, 3), 256>>>(x, Wq, Wk, Wv);
    attn_split_kernel<<<dim3(T_ / 64, SPLITS, B_), 256, attn_smem>>>();
    combine_kernel<<<(B_ * T_) / 16, 256>>>(out);
}

// round 7
// speedup vs baseline: 1.5509x; 1.1350x over previous
#include <cuda_runtime.h>
#include <cuda_bf16.h>
#include <cstdint>

#define B_ 4
#define T_ 4096
#define C_ 1024
#define H_ 64
#define SPLITS 4
#define NEG_BIG (-1e30f)

// Scratch: projected Q, K, V [B,T,H] fp32.
__device__ float g_Q[B_ * T_ * H_];
__device__ float g_K[B_ * T_ * H_];
__device__ float g_V[B_ * T_ * H_];
// Split-K attention partials.
__device__ float g_opart[SPLITS][B_ * T_ * H_];
__device__ float g_m[SPLITS][B_ * T_];
__device__ float g_l[SPLITS][B_ * T_];

// ---------------- packed f32x2 helpers (attention kernels) -----------------
__device__ __forceinline__ unsigned long long pk2(float lo, float hi) {
    unsigned long long r;
    asm("mov.b64 %0, {%1, %2};" : "=l"(r) : "f"(lo), "f"(hi));
    return r;
}
__device__ __forceinline__ float2 upk(unsigned long long v) {
    float2 r;
    asm("mov.b64 {%0, %1}, %2;" : "=f"(r.x), "=f"(r.y) : "l"(v));
    return r;
}
__device__ __forceinline__ void ffma2(unsigned long long& d,
                                      unsigned long long a,
                                      unsigned long long b) {
    asm("fma.rn.f32x2 %0, %1, %2, %0;" : "+l"(d) : "l"(a), "l"(b));
}
__device__ __forceinline__ void fmul2(unsigned long long& d,
                                      unsigned long long a) {
    asm("mul.rn.f32x2 %0, %0, %1;" : "+l"(d) : "l"(a));
}

// ---------------- bf16 hi/lo split + HMMA mma.sync helpers -----------------
// hi/lo bf16 split of two fp32 values, packed as bf16x2 words (low = first).
__device__ __forceinline__ void cvt_pair(float a, float b,
                                         uint32_t& hi, uint32_t& lo) {
    __nv_bfloat16 ha = __float2bfloat16(a);
    __nv_bfloat16 hb = __float2bfloat16(b);
    __nv_bfloat16 la = __float2bfloat16(a - __bfloat162float(ha));
    __nv_bfloat16 lb = __float2bfloat16(b - __bfloat162float(hb));
    hi = (uint32_t)__bfloat16_as_ushort(ha) |
         ((uint32_t)__bfloat16_as_ushort(hb) << 16);
    lo = (uint32_t)__bfloat16_as_ushort(la) |
         ((uint32_t)__bfloat16_as_ushort(lb) << 16);
}

__device__ __forceinline__ void mma16816(float* d, const uint32_t* a,
                                         uint32_t b0, uint32_t b1) {
    asm volatile(
        "mma.sync.aligned.m16n8k16.row.col.f32.bf16.bf16.f32 "
        "{%0,%1,%2,%3}, {%4,%5,%6,%7}, {%8,%9}, {%0,%1,%2,%3};"
        : "+f"(d[0]), "+f"(d[1]), "+f"(d[2]), "+f"(d[3])
        : "r"(a[0]), "r"(a[1]), "r"(a[2]), "r"(a[3]), "r"(b0), "r"(b1));
}

// ---------------------------------------------------------------------------
// Kernel 1: fused QKV projection via HMMA (mma.sync bf16, hi/lo 3-term split).
// D[M=16384, N=192] = x @ [Wq;Wk;Wv]^T.  Grid (128 M-tiles, 3 N-tiles of 64).
// Block 256 = 8 warps (4x2), warp tile 32x32, k-chunks of 64 fp32 columns.
// smem (bf16, row stride 72 for conflict-free fragment LDS):
//   Ahi[128][72], Alo[128][72], Bhi[64][72], Blo[64][72]  = 55296 B.
// ---------------------------------------------------------------------------
#define APAD 72
#define SM_ALO (128 * APAD)
#define SM_BHI (2 * 128 * APAD)
#define SM_BLO (2 * 128 * APAD + 64 * APAD)
#define PROJ_SMEM ((2 * 128 * APAD + 2 * 64 * APAD) * 2)

__global__ __launch_bounds__(256, 1)
void proj_mma_kernel(const float* __restrict__ x,
                     const float* __restrict__ Wq,
                     const float* __restrict__ Wk,
                     const float* __restrict__ Wv) {
    extern __shared__ __nv_bfloat16 sb[];
    __nv_bfloat16* Ahi = sb;
    __nv_bfloat16* Alo = sb + SM_ALO;
    __nv_bfloat16* Bhi = sb + SM_BHI;
    __nv_bfloat16* Blo = sb + SM_BLO;

    const int t    = threadIdx.x;
    const int wid  = t >> 5;
    const int lane = t & 31;
    const int row0 = blockIdx.x * 128;
    const int nt   = blockIdx.y;

    const float* W = (nt == 0) ? Wq : (nt == 1) ? Wk : Wv;
    float* dst     = (nt == 0) ? g_Q : (nt == 1) ? g_K : g_V;

    // loader mapping
    const int ar = t >> 1, ac = (t & 1) * 32;   // A: row ar, 8 float4
    const int br = t >> 2, bc = (t & 3) * 16;   // B: row br, 4 float4

    // warp tile mapping
    const int wm = wid >> 1, wn = wid & 1;
    const int g = lane >> 2, c = lane & 3;

    float acc[2][4][4] = {};

    for (int kc = 0; kc < C_; kc += 64) {
        // ---- convert & store x chunk (hi/lo) ----
        {
            const float* src = x + (size_t)(row0 + ar) * C_ + kc + ac;
            #pragma unroll
            for (int u = 0; u < 8; u++) {
                const float4 v = *(const float4*)(src + u * 4);
                uint32_t h01, l01, h23, l23;
                cvt_pair(v.x, v.y, h01, l01);
                cvt_pair(v.z, v.w, h23, l23);
                const int col = ac + u * 4;
                *(uint2*)(Ahi + ar * APAD + col) = make_uint2(h01, h23);
                *(uint2*)(Alo + ar * APAD + col) = make_uint2(l01, l23);
            }
        }
        // ---- convert & store W chunk (hi/lo) ----
        {
            const float* src = W + (size_t)br * C_ + kc + bc;
            #pragma unroll
            for (int u = 0; u < 4; u++) {
                const float4 v = *(const float4*)(src + u * 4);
                uint32_t h01, l01, h23, l23;
                cvt_pair(v.x, v.y, h01, l01);
                cvt_pair(v.z, v.w, h23, l23);
                const int col = bc + u * 4;
                *(uint2*)(Bhi + br * APAD + col) = make_uint2(h01, h23);
                *(uint2*)(Blo + br * APAD + col) = make_uint2(l01, l23);
            }
        }
        __syncthreads();

        // ---- 3 passes (hh, hl, lh) x 4 k16 steps of HMMA ----
        #pragma unroll
        for (int pass = 0; pass < 3; pass++) {
            const __nv_bfloat16* As = (pass == 2) ? Alo : Ahi;
            const __nv_bfloat16* Bs = (pass == 1) ? Blo : Bhi;
            #pragma unroll
            for (int k16 = 0; k16 < 4; k16++) {
                const int kb = k16 * 16;
                uint32_t a[2][4];
                #pragma unroll
                for (int mi = 0; mi < 2; mi++) {
                    const __nv_bfloat16* base =
                        As + (wm * 32 + mi * 16 + g) * APAD + kb + c * 2;
                    a[mi][0] = *(const uint32_t*)(base);
                    a[mi][1] = *(const uint32_t*)(base + 8 * APAD);
                    a[mi][2] = *(const uint32_t*)(base + 8);
                    a[mi][3] = *(const uint32_t*)(base + 8 * APAD + 8);
                }
                #pragma unroll
                for (int ni = 0; ni < 4; ni++) {
                    const __nv_bfloat16* bb =
                        Bs + (wn * 32 + ni * 8 + g) * APAD + kb + c * 2;
                    const uint32_t b0 = *(const uint32_t*)(bb);
                    const uint32_t b1 = *(const uint32_t*)(bb + 8);
                    mma16816(acc[0][ni], a[0], b0, b1);
                    mma16816(acc[1][ni], a[1], b0, b1);
                }
            }
        }
        __syncthreads();
    }

    // ---- epilogue: fragment -> fp32 global (H_ = 64 columns per dst) ----
    #pragma unroll
    for (int mi = 0; mi < 2; mi++) {
        const int r = row0 + wm * 32 + mi * 16 + g;
        #pragma unroll
        for (int ni = 0; ni < 4; ni++) {
            const int col = wn * 32 + ni * 8 + c * 2;
            float2 v0; v0.x = acc[mi][ni][0]; v0.y = acc[mi][ni][1];
            float2 v1; v1.x = acc[mi][ni][2]; v1.y = acc[mi][ni][3];
            *(float2*)(dst + (size_t)r * H_ + col) = v0;
            *(float2*)(dst + (size_t)(r + 8) * H_ + col) = v1;
        }
    }
}

// ---------------------------------------------------------------------------
// Kernel 2: split-K flash attention (unchanged — proven at ~350 us).
// ---------------------------------------------------------------------------
__global__ __launch_bounds__(256)
void attn_split_kernel() {
    extern __shared__ float sm[];
    float* q_s  = sm;
    float* kp_s = sm + 4096;
    float* v_s  = sm + 8192;

    const int qb = blockIdx.x;
    const int sp = blockIdx.y;
    const int b  = blockIdx.z;
    const int t  = threadIdx.x;
    const int tx = t >> 4;
    const int ty = t & 15;
    const int lr = t >> 2;
    const int lh = (t & 3) * 16;

    const size_t base = (size_t)b * T_ * H_;

    {
        const float* src = g_Q + base + (size_t)(qb * 64 + lr) * H_ + lh;
        #pragma unroll
        for (int u = 0; u < 4; u++) {
            const float4 v = *(const float4*)(src + u * 4);
            q_s[(lh + u * 4 + 0) * 64 + lr] = v.x;
            q_s[(lh + u * 4 + 1) * 64 + lr] = v.y;
            q_s[(lh + u * 4 + 2) * 64 + lr] = v.z;
            q_s[(lh + u * 4 + 3) * 64 + lr] = v.w;
        }
    }

    unsigned long long o2[4][2] = {};
    float m[4], l[4];
    #pragma unroll
    for (int i = 0; i < 4; i++) { m[i] = NEG_BIG; l[i] = 0.0f; }

    const int kb_max = min(qb + 1, T_ / 64 - 1);
    const float sc2 = 1.0f / 64.0f;

    for (int kb = sp; kb <= kb_max; kb += SPLITS) {
        {
            const float* ksrc = g_K + base + (size_t)(kb * 64 + lr) * H_ + lh;
            const float* vsrc = g_V + base + (size_t)(kb * 64 + lr) * H_ + lh;
            #pragma unroll
            for (int u = 0; u < 4; u++) {
                const float4 kv = *(const float4*)(ksrc + u * 4);
                const int h0 = lh + u * 4;
                const int jq = lr >> 2, jw = lr & 3;
                kp_s[(h0 + 0) * 64 + ((jq ^ ((h0 + 0) & 15)) << 2) + jw] = kv.x;
                kp_s[(h0 + 1) * 64 + ((jq ^ ((h0 + 1) & 15)) << 2) + jw] = kv.y;
                kp_s[(h0 + 2) * 64 + ((jq ^ ((h0 + 2) & 15)) << 2) + jw] = kv.z;
                kp_s[(h0 + 3) * 64 + ((jq ^ ((h0 + 3) & 15)) << 2) + jw] = kv.w;
                *(float4*)(v_s + lr * 64 + h0) = *(const float4*)(vsrc + u * 4);
            }
        }
        __syncthreads();

        unsigned long long s2[4][2] = {};
        #pragma unroll 4
        for (int h = 0; h < 64; h++) {
            const float4 qf = *(const float4*)(q_s + h * 64 + tx * 4);
            const ulonglong2 kk = *(const ulonglong2*)
                (kp_s + h * 64 + ((ty ^ (h & 15)) << 2));
            const unsigned long long q0 = pk2(qf.x, qf.x);
            const unsigned long long q1 = pk2(qf.y, qf.y);
            const unsigned long long q2 = pk2(qf.z, qf.z);
            const unsigned long long q3 = pk2(qf.w, qf.w);
            ffma2(s2[0][0], q0, kk.x); ffma2(s2[0][1], q0, kk.y);
            ffma2(s2[1][0], q1, kk.x); ffma2(s2[1][1], q1, kk.y);
            ffma2(s2[2][0], q2, kk.x); ffma2(s2[2][1], q2, kk.y);
            ffma2(s2[3][0], q3, kk.x); ffma2(s2[3][1], q3, kk.y);
        }
        __syncthreads();

        float e[4][4], fac[4];
        #pragma unroll
        for (int i = 0; i < 4; i++) {
            const float2 pa = upk(s2[i][0]);
            const float2 pb = upk(s2[i][1]);
            float sv[4] = { pa.x, pa.y, pb.x, pb.y };
            const int gi = qb * 64 + tx * 4 + i;
            bool al[4];
            float rm = NEG_BIG;
            #pragma unroll
            for (int j = 0; j < 4; j++) {
                const int gj = kb * 64 + ty * 4 + j;
                al[j] = (gj <= gi + 1);
                sv[j] = al[j] ? sv[j] * sc2 : NEG_BIG;
                rm = fmaxf(rm, sv[j]);
            }
            rm = fmaxf(rm, __shfl_xor_sync(0xffffffffu, rm, 1, 16));
            rm = fmaxf(rm, __shfl_xor_sync(0xffffffffu, rm, 2, 16));
            rm = fmaxf(rm, __shfl_xor_sync(0xffffffffu, rm, 4, 16));
            rm = fmaxf(rm, __shfl_xor_sync(0xffffffffu, rm, 8, 16));
            const float mn = fmaxf(m[i], rm);
            fac[i] = __expf(m[i] - mn);
            float rs = 0.0f;
            #pragma unroll
            for (int j = 0; j < 4; j++) {
                const float ev = al[j] ? __expf(sv[j] - mn) : 0.0f;
                e[i][j] = ev;
                rs += ev;
            }
            rs += __shfl_xor_sync(0xffffffffu, rs, 1, 16);
            rs += __shfl_xor_sync(0xffffffffu, rs, 2, 16);
            rs += __shfl_xor_sync(0xffffffffu, rs, 4, 16);
            rs += __shfl_xor_sync(0xffffffffu, rs, 8, 16);
            l[i] = l[i] * fac[i] + rs;
            m[i] = mn;
        }

        #pragma unroll
        for (int i = 0; i < 4; i++) {
            const unsigned long long f2 = pk2(fac[i], fac[i]);
            fmul2(o2[i][0], f2);
            fmul2(o2[i][1], f2);
        }

        #pragma unroll
        for (int i = 0; i < 4; i++) {
            float4 pv;
            pv.x = e[i][0]; pv.y = e[i][1]; pv.z = e[i][2]; pv.w = e[i][3];
            *(float4*)(kp_s + (tx * 4 + i) * 64 + ty * 4) = pv;
        }
        __syncthreads();

        #pragma unroll 2
        for (int jc = 0; jc < 16; jc++) {
            float pa[4][4];
            #pragma unroll
            for (int i = 0; i < 4; i++)
                *(float4*)pa[i] = *(const float4*)(kp_s + (tx * 4 + i) * 64 + jc * 4);
            ulonglong2 vb[4];
            #pragma unroll
            for (int u = 0; u < 4; u++)
                vb[u] = *(const ulonglong2*)(v_s + (jc * 4 + u) * 64 + ty * 4);
            #pragma unroll
            for (int u = 0; u < 4; u++) {
                #pragma unroll
                for (int i = 0; i < 4; i++) {
                    const unsigned long long pd = pk2(pa[i][u], pa[i][u]);
                    ffma2(o2[i][0], pd, vb[u].x);
                    ffma2(o2[i][1], pd, vb[u].y);
                }
            }
        }
        __syncthreads();
    }

    const size_t rb = (size_t)b * T_ + qb * 64;
    #pragma unroll
    for (int i = 0; i < 4; i++) {
        const float2 a = upk(o2[i][0]);
        const float2 c = upk(o2[i][1]);
        float4 ov; ov.x = a.x; ov.y = a.y; ov.z = c.x; ov.w = c.y;
        *(float4*)(g_opart[sp] + (rb + tx * 4 + i) * 64 + ty * 4) = ov;
    }
    if (ty == 0) {
        #pragma unroll
        for (int i = 0; i < 4; i++) {
            g_m[sp][rb + tx * 4 + i] = m[i];
            g_l[sp][rb + tx * 4 + i] = l[i];
        }
    }
}

// ---------------------------------------------------------------------------
// Kernel 3: combine split partials (unchanged).
// ---------------------------------------------------------------------------
__global__ __launch_bounds__(256)
void combine_kernel(float* __restrict__ out) {
    const int t = threadIdx.x;
    const size_t r = (size_t)blockIdx.x * 16 + (t >> 4);
    const int c = (t & 15) * 4;

    float mv[SPLITS], lv[SPLITS];
    float M = NEG_BIG;
    #pragma unroll
    for (int s = 0; s < SPLITS; s++) {
        mv[s] = g_m[s][r];
        lv[s] = g_l[s][r];
        M = fmaxf(M, mv[s]);
    }
    float w[SPLITS], L = 0.0f;
    #pragma unroll
    for (int s = 0; s < SPLITS; s++) {
        w[s] = __expf(mv[s] - M);
        L += lv[s] * w[s];
    }
    float4 acc = make_float4(0.f, 0.f, 0.f, 0.f);
    #pragma unroll
    for (int s = 0; s < SPLITS; s++) {
        const float4 o = *(const float4*)(g_opart[s] + r * 64 + c);
        acc.x += w[s] * o.x; acc.y += w[s] * o.y;
        acc.z += w[s] * o.z; acc.w += w[s] * o.w;
    }
    const float inv = 1.0f / L;
    float4 ov;
    ov.x = acc.x * inv; ov.y = acc.y * inv;
    ov.z = acc.z * inv; ov.w = acc.w * inv;
    *(float4*)(out + r * 64 + c) = ov;
}

// ---------------------------------------------------------------------------
// Launch
// ---------------------------------------------------------------------------
extern "C" void kernel_launch(void* const* d_in, const int* in_sizes, int n_in,
                              void* d_out, int out_size) {
    const float* x  = (const float*)d_in[0];
    const float* Wk = (const float*)d_in[1];
    const float* Wq = (const float*)d_in[2];
    const float* Wv = (const float*)d_in[3];
    float* out = (float*)d_out;

    cudaFuncSetAttribute(proj_mma_kernel,
                         cudaFuncAttributeMaxDynamicSharedMemorySize, PROJ_SMEM);
    const int attn_smem = 3 * 64 * 64 * (int)sizeof(float);
    cudaFuncSetAttribute(attn_split_kernel,
                         cudaFuncAttributeMaxDynamicSharedMemorySize, attn_smem);

    proj_mma_kernel<<<dim3((B_ * T_) / 128, 3), 256, PROJ_SMEM>>>(x, Wq, Wk, Wv);
    attn_split_kernel<<<dim3(T_ / 64, SPLITS, B_), 256, attn_smem>>>();
    combine_kernel<<<(B_ * T_) / 16, 256>>>(out);
}

// round 8
// speedup vs baseline: 2.8273x; 1.8230x over previous
#include <cuda_runtime.h>
#include <cuda_bf16.h>
#include <cstdint>

#define B_ 4
#define T_ 4096
#define C_ 1024
#define H_ 64
#define SPLITS 4
#define NEG_BIG (-1e30f)

// Projected Q, K bf16 hi/lo [B,T,64]; V transposed hi/lo [B,64,T].
__device__ __nv_bfloat16 g_Qh[B_ * T_ * H_];
__device__ __nv_bfloat16 g_Ql[B_ * T_ * H_];
__device__ __nv_bfloat16 g_Kh[B_ * T_ * H_];
__device__ __nv_bfloat16 g_Kl[B_ * T_ * H_];
__device__ __nv_bfloat16 g_Vth[B_ * H_ * T_];
__device__ __nv_bfloat16 g_Vtl[B_ * H_ * T_];
// Split-K attention partials.
__device__ float g_opart[SPLITS][B_ * T_ * H_];
__device__ float g_m[SPLITS][B_ * T_];
__device__ float g_l[SPLITS][B_ * T_];

// ---------------- bf16 hi/lo split + HMMA mma.sync helpers -----------------
__device__ __forceinline__ void cvt_pair(float a, float b,
                                         uint32_t& hi, uint32_t& lo) {
    __nv_bfloat16 ha = __float2bfloat16(a);
    __nv_bfloat16 hb = __float2bfloat16(b);
    __nv_bfloat16 la = __float2bfloat16(a - __bfloat162float(ha));
    __nv_bfloat16 lb = __float2bfloat16(b - __bfloat162float(hb));
    hi = (uint32_t)__bfloat16_as_ushort(ha) |
         ((uint32_t)__bfloat16_as_ushort(hb) << 16);
    lo = (uint32_t)__bfloat16_as_ushort(la) |
         ((uint32_t)__bfloat16_as_ushort(lb) << 16);
}
__device__ __forceinline__ void cvt_one(float a, uint16_t& hi, uint16_t& lo) {
    __nv_bfloat16 ha = __float2bfloat16(a);
    __nv_bfloat16 la = __float2bfloat16(a - __bfloat162float(ha));
    hi = __bfloat16_as_ushort(ha);
    lo = __bfloat16_as_ushort(la);
}

__device__ __forceinline__ void mma16816(float* d, const uint32_t* a,
                                         uint32_t b0, uint32_t b1) {
    asm volatile(
        "mma.sync.aligned.m16n8k16.row.col.f32.bf16.bf16.f32 "
        "{%0,%1,%2,%3}, {%4,%5,%6,%7}, {%8,%9}, {%0,%1,%2,%3};"
        : "+f"(d[0]), "+f"(d[1]), "+f"(d[2]), "+f"(d[3])
        : "r"(a[0]), "r"(a[1]), "r"(a[2]), "r"(a[3]), "r"(b0), "r"(b1));
}

// ---------------------------------------------------------------------------
// Kernel 1: fused QKV projection via HMMA, outputs bf16 hi/lo.
// Grid (128 M-tiles, 3 N-tiles of 64).  Block 256 = 8 warps (4x2).
// ---------------------------------------------------------------------------
#define APAD 72
#define SM_ALO (128 * APAD)
#define SM_BHI (2 * 128 * APAD)
#define SM_BLO (2 * 128 * APAD + 64 * APAD)
#define PROJ_SMEM ((2 * 128 * APAD + 2 * 64 * APAD) * 2)

__global__ __launch_bounds__(256, 2)
void proj_mma_kernel(const float* __restrict__ x,
                     const float* __restrict__ Wq,
                     const float* __restrict__ Wk,
                     const float* __restrict__ Wv) {
    extern __shared__ __nv_bfloat16 sb[];
    __nv_bfloat16* Ahi = sb;
    __nv_bfloat16* Alo = sb + SM_ALO;
    __nv_bfloat16* Bhi = sb + SM_BHI;
    __nv_bfloat16* Blo = sb + SM_BLO;

    const int t    = threadIdx.x;
    const int wid  = t >> 5;
    const int lane = t & 31;
    const int row0 = blockIdx.x * 128;
    const int nt   = blockIdx.y;

    const float* W = (nt == 0) ? Wq : (nt == 1) ? Wk : Wv;

    const int ar = t >> 1, ac = (t & 1) * 32;
    const int br = t >> 2, bc = (t & 3) * 16;
    const int wm = wid >> 1, wn = wid & 1;
    const int g = lane >> 2, c = lane & 3;

    float acc[2][4][4] = {};

    for (int kc = 0; kc < C_; kc += 64) {
        {
            const float* src = x + (size_t)(row0 + ar) * C_ + kc + ac;
            #pragma unroll
            for (int u = 0; u < 8; u++) {
                const float4 v = *(const float4*)(src + u * 4);
                uint32_t h01, l01, h23, l23;
                cvt_pair(v.x, v.y, h01, l01);
                cvt_pair(v.z, v.w, h23, l23);
                const int col = ac + u * 4;
                *(uint2*)(Ahi + ar * APAD + col) = make_uint2(h01, h23);
                *(uint2*)(Alo + ar * APAD + col) = make_uint2(l01, l23);
            }
        }
        {
            const float* src = W + (size_t)br * C_ + kc + bc;
            #pragma unroll
            for (int u = 0; u < 4; u++) {
                const float4 v = *(const float4*)(src + u * 4);
                uint32_t h01, l01, h23, l23;
                cvt_pair(v.x, v.y, h01, l01);
                cvt_pair(v.z, v.w, h23, l23);
                const int col = bc + u * 4;
                *(uint2*)(Bhi + br * APAD + col) = make_uint2(h01, h23);
                *(uint2*)(Blo + br * APAD + col) = make_uint2(l01, l23);
            }
        }
        __syncthreads();

        #pragma unroll
        for (int pass = 0; pass < 3; pass++) {
            const __nv_bfloat16* As = (pass == 2) ? Alo : Ahi;
            const __nv_bfloat16* Bs = (pass == 1) ? Blo : Bhi;
            #pragma unroll
            for (int k16 = 0; k16 < 4; k16++) {
                const int kb = k16 * 16;
                uint32_t a[2][4];
                #pragma unroll
                for (int mi = 0; mi < 2; mi++) {
                    const __nv_bfloat16* base =
                        As + (wm * 32 + mi * 16 + g) * APAD + kb + c * 2;
                    a[mi][0] = *(const uint32_t*)(base);
                    a[mi][1] = *(const uint32_t*)(base + 8 * APAD);
                    a[mi][2] = *(const uint32_t*)(base + 8);
                    a[mi][3] = *(const uint32_t*)(base + 8 * APAD + 8);
                }
                #pragma unroll
                for (int ni = 0; ni < 4; ni++) {
                    const __nv_bfloat16* bb =
                        Bs + (wn * 32 + ni * 8 + g) * APAD + kb + c * 2;
                    const uint32_t b0 = *(const uint32_t*)(bb);
                    const uint32_t b1 = *(const uint32_t*)(bb + 8);
                    mma16816(acc[0][ni], a[0], b0, b1);
                    mma16816(acc[1][ni], a[1], b0, b1);
                }
            }
        }
        __syncthreads();
    }

    // ---- epilogue: convert to bf16 hi/lo and store ----
    if (nt < 2) {
        __nv_bfloat16* dh = (nt == 0) ? g_Qh : g_Kh;
        __nv_bfloat16* dl = (nt == 0) ? g_Ql : g_Kl;
        #pragma unroll
        for (int mi = 0; mi < 2; mi++) {
            const int r = row0 + wm * 32 + mi * 16 + g;
            #pragma unroll
            for (int ni = 0; ni < 4; ni++) {
                const int col = wn * 32 + ni * 8 + c * 2;
                uint32_t h01, l01, h23, l23;
                cvt_pair(acc[mi][ni][0], acc[mi][ni][1], h01, l01);
                cvt_pair(acc[mi][ni][2], acc[mi][ni][3], h23, l23);
                *(uint32_t*)(dh + (size_t)r * H_ + col) = h01;
                *(uint32_t*)(dl + (size_t)r * H_ + col) = l01;
                *(uint32_t*)(dh + (size_t)(r + 8) * H_ + col) = h23;
                *(uint32_t*)(dl + (size_t)(r + 8) * H_ + col) = l23;
            }
        }
    } else {
        // V transposed: g_Vt[b][c][t]
        #pragma unroll
        for (int mi = 0; mi < 2; mi++) {
            const int r = row0 + wm * 32 + mi * 16 + g;
            const int bb = r >> 12;
            const int tt = r & (T_ - 1);
            #pragma unroll
            for (int ni = 0; ni < 4; ni++) {
                const int col = wn * 32 + ni * 8 + c * 2;
                #pragma unroll
                for (int u = 0; u < 4; u++) {
                    const int rr = (u >> 1) * 8;          // 0 or 8
                    const int cc = col + (u & 1);
                    uint16_t h, l;
                    cvt_one(acc[mi][ni][u], h, l);
                    const size_t idx =
                        ((size_t)bb * H_ + cc) * T_ + tt + rr;
                    *(uint16_t*)(g_Vth + idx) = h;
                    *(uint16_t*)(g_Vtl + idx) = l;
                }
            }
        }
    }
}

// ---------------------------------------------------------------------------
// Kernel 2: split-K flash attention on HMMA (bf16 hi/lo 3-term splits).
// Grid (64 qb, SPLITS, 4 b). Block 256 = 8 warps (wm 0-3 x wn 0-1).
// smem: Kh,Kl,Vh,Vl,Ph,Pl tiles 64x72 bf16 + reduction arrays = 56320 B.
// ---------------------------------------------------------------------------
#define TPAD 72
#define ATTN_SMEM (6 * 64 * TPAD * 2 + 2 * 128 * 4)

__global__ __launch_bounds__(256, 1)
void attn_mma_kernel() {
    extern __shared__ char smraw[];
    __nv_bfloat16* Khs = (__nv_bfloat16*)smraw;
    __nv_bfloat16* Kls = Khs + 64 * TPAD;
    __nv_bfloat16* Vhs = Kls + 64 * TPAD;
    __nv_bfloat16* Vls = Vhs + 64 * TPAD;
    __nv_bfloat16* Phs = Vls + 64 * TPAD;
    __nv_bfloat16* Pls = Phs + 64 * TPAD;
    float* redmax = (float*)(Pls + 64 * TPAD);   // [64][2]
    float* redsum = redmax + 128;                // [64][2]

    const int qb = blockIdx.x, sp = blockIdx.y, b = blockIdx.z;
    const int t = threadIdx.x, wid = t >> 5, lane = t & 31;
    const int wm = wid >> 1, wn = wid & 1;
    const int g = lane >> 2, c = lane & 3;
    const int lr = t >> 2, lc = (t & 3) * 16;

    const size_t base = (size_t)b * T_ * H_;
    const int row_a = wm * 16 + g;               // this thread's first S row

    // ---- stage Q tile into Phs/Pls, pull A-fragments into registers ----
    {
        const size_t off = base + (size_t)(qb * 64 + lr) * H_ + lc;
        *(uint4*)(Phs + lr * TPAD + lc)     = *(const uint4*)(g_Qh + off);
        *(uint4*)(Phs + lr * TPAD + lc + 8) = *(const uint4*)(g_Qh + off + 8);
        *(uint4*)(Pls + lr * TPAD + lc)     = *(const uint4*)(g_Ql + off);
        *(uint4*)(Pls + lr * TPAD + lc + 8) = *(const uint4*)(g_Ql + off + 8);
    }
    __syncthreads();
    uint32_t qh_f[4][4], ql_f[4][4];
    #pragma unroll
    for (int k = 0; k < 4; k++) {
        const __nv_bfloat16* ba = Phs + row_a * TPAD + k * 16 + c * 2;
        qh_f[k][0] = *(const uint32_t*)(ba);
        qh_f[k][1] = *(const uint32_t*)(ba + 8 * TPAD);
        qh_f[k][2] = *(const uint32_t*)(ba + 8);
        qh_f[k][3] = *(const uint32_t*)(ba + 8 * TPAD + 8);
        const __nv_bfloat16* bl = Pls + row_a * TPAD + k * 16 + c * 2;
        ql_f[k][0] = *(const uint32_t*)(bl);
        ql_f[k][1] = *(const uint32_t*)(bl + 8 * TPAD);
        ql_f[k][2] = *(const uint32_t*)(bl + 8);
        ql_f[k][3] = *(const uint32_t*)(bl + 8 * TPAD + 8);
    }
    __syncthreads();

    float o_acc[4][4] = {};
    float m0 = NEG_BIG, m1 = NEG_BIG, l0 = 0.0f, l1 = 0.0f;
    const float sc2 = 1.0f / 64.0f;
    const int kb_max = min(qb + 1, T_ / 64 - 1);

    for (int kb = sp; kb <= kb_max; kb += SPLITS) {
        // ---- load K tile [j][h] and Vt tile [c][j] (hi/lo) ----
        {
            const size_t koff = base + (size_t)(kb * 64 + lr) * H_ + lc;
            *(uint4*)(Khs + lr * TPAD + lc)     = *(const uint4*)(g_Kh + koff);
            *(uint4*)(Khs + lr * TPAD + lc + 8) = *(const uint4*)(g_Kh + koff + 8);
            *(uint4*)(Kls + lr * TPAD + lc)     = *(const uint4*)(g_Kl + koff);
            *(uint4*)(Kls + lr * TPAD + lc + 8) = *(const uint4*)(g_Kl + koff + 8);
            const size_t voff = ((size_t)b * H_ + lr) * T_ + kb * 64 + lc;
            *(uint4*)(Vhs + lr * TPAD + lc)     = *(const uint4*)(g_Vth + voff);
            *(uint4*)(Vhs + lr * TPAD + lc + 8) = *(const uint4*)(g_Vth + voff + 8);
            *(uint4*)(Vls + lr * TPAD + lc)     = *(const uint4*)(g_Vtl + voff);
            *(uint4*)(Vls + lr * TPAD + lc + 8) = *(const uint4*)(g_Vtl + voff + 8);
        }
        __syncthreads();

        // ---- S = Q K^T, 3 passes (hh, hl, lh) ----
        float s_acc[4][4] = {};
        #pragma unroll
        for (int k = 0; k < 4; k++) {
            #pragma unroll
            for (int ni = 0; ni < 4; ni++) {
                const int brow = (wn * 32 + ni * 8 + g) * TPAD + k * 16 + c * 2;
                const uint32_t bh0 = *(const uint32_t*)(Khs + brow);
                const uint32_t bh1 = *(const uint32_t*)(Khs + brow + 8);
                const uint32_t bl0 = *(const uint32_t*)(Kls + brow);
                const uint32_t bl1 = *(const uint32_t*)(Kls + brow + 8);
                mma16816(s_acc[ni], qh_f[k], bh0, bh1);
                mma16816(s_acc[ni], qh_f[k], bl0, bl1);
                mma16816(s_acc[ni], ql_f[k], bh0, bh1);
            }
        }

        // ---- scale + mask + row max ----
        const bool need_mask = (kb >= qb);
        const int i0 = qb * 64 + row_a;
        float sv[4][4];
        float rm0 = NEG_BIG, rm1 = NEG_BIG;
        #pragma unroll
        for (int ni = 0; ni < 4; ni++) {
            const int j0 = kb * 64 + wn * 32 + ni * 8 + c * 2;
            float v0 = s_acc[ni][0] * sc2;
            float v1 = s_acc[ni][1] * sc2;
            float v2 = s_acc[ni][2] * sc2;
            float v3 = s_acc[ni][3] * sc2;
            if (need_mask) {
                if (j0     > i0 + 1) v0 = NEG_BIG;
                if (j0 + 1 > i0 + 1) v1 = NEG_BIG;
                if (j0     > i0 + 9) v2 = NEG_BIG;
                if (j0 + 1 > i0 + 9) v3 = NEG_BIG;
            }
            sv[ni][0] = v0; sv[ni][1] = v1; sv[ni][2] = v2; sv[ni][3] = v3;
            rm0 = fmaxf(rm0, fmaxf(v0, v1));
            rm1 = fmaxf(rm1, fmaxf(v2, v3));
        }
        rm0 = fmaxf(rm0, __shfl_xor_sync(0xffffffffu, rm0, 1));
        rm0 = fmaxf(rm0, __shfl_xor_sync(0xffffffffu, rm0, 2));
        rm1 = fmaxf(rm1, __shfl_xor_sync(0xffffffffu, rm1, 1));
        rm1 = fmaxf(rm1, __shfl_xor_sync(0xffffffffu, rm1, 2));
        redmax[(row_a)     * 2 + wn] = rm0;
        redmax[(row_a + 8) * 2 + wn] = rm1;
        __syncthreads();
        rm0 = fmaxf(redmax[row_a * 2], redmax[row_a * 2 + 1]);
        rm1 = fmaxf(redmax[(row_a + 8) * 2], redmax[(row_a + 8) * 2 + 1]);
        const float mn0 = fmaxf(m0, rm0);
        const float mn1 = fmaxf(m1, rm1);
        const float f0 = __expf(m0 - mn0);
        const float f1 = __expf(m1 - mn1);
        m0 = mn0; m1 = mn1;

        // ---- exp, row sum, P -> bf16 hi/lo smem ----
        float rs0 = 0.0f, rs1 = 0.0f;
        #pragma unroll
        for (int ni = 0; ni < 4; ni++) {
            const float e0 = (sv[ni][0] > -5e29f) ? __expf(sv[ni][0] - mn0) : 0.0f;
            const float e1 = (sv[ni][1] > -5e29f) ? __expf(sv[ni][1] - mn0) : 0.0f;
            const float e2 = (sv[ni][2] > -5e29f) ? __expf(sv[ni][2] - mn1) : 0.0f;
            const float e3 = (sv[ni][3] > -5e29f) ? __expf(sv[ni][3] - mn1) : 0.0f;
            rs0 += e0 + e1;
            rs1 += e2 + e3;
            uint32_t h01, l01, h23, l23;
            cvt_pair(e0, e1, h01, l01);
            cvt_pair(e2, e3, h23, l23);
            const int col = wn * 32 + ni * 8 + c * 2;
            *(uint32_t*)(Phs + (row_a)     * TPAD + col) = h01;
            *(uint32_t*)(Pls + (row_a)     * TPAD + col) = l01;
            *(uint32_t*)(Phs + (row_a + 8) * TPAD + col) = h23;
            *(uint32_t*)(Pls + (row_a + 8) * TPAD + col) = l23;
        }
        rs0 += __shfl_xor_sync(0xffffffffu, rs0, 1);
        rs0 += __shfl_xor_sync(0xffffffffu, rs0, 2);
        rs1 += __shfl_xor_sync(0xffffffffu, rs1, 1);
        rs1 += __shfl_xor_sync(0xffffffffu, rs1, 2);
        redsum[(row_a)     * 2 + wn] = rs0;
        redsum[(row_a + 8) * 2 + wn] = rs1;

        // rescale accumulators while stores land
        #pragma unroll
        for (int ni = 0; ni < 4; ni++) {
            o_acc[ni][0] *= f0; o_acc[ni][1] *= f0;
            o_acc[ni][2] *= f1; o_acc[ni][3] *= f1;
        }
        __syncthreads();
        l0 = l0 * f0 + redsum[row_a * 2] + redsum[row_a * 2 + 1];
        l1 = l1 * f1 + redsum[(row_a + 8) * 2] + redsum[(row_a + 8) * 2 + 1];

        // ---- O += P V, 3 passes (Ph*Vh, Ph*Vl, Pl*Vh) ----
        #pragma unroll
        for (int k = 0; k < 4; k++) {
            uint32_t ph[4], pl[4];
            const __nv_bfloat16* pa = Phs + row_a * TPAD + k * 16 + c * 2;
            ph[0] = *(const uint32_t*)(pa);
            ph[1] = *(const uint32_t*)(pa + 8 * TPAD);
            ph[2] = *(const uint32_t*)(pa + 8);
            ph[3] = *(const uint32_t*)(pa + 8 * TPAD + 8);
            const __nv_bfloat16* pb = Pls + row_a * TPAD + k * 16 + c * 2;
            pl[0] = *(const uint32_t*)(pb);
            pl[1] = *(const uint32_t*)(pb + 8 * TPAD);
            pl[2] = *(const uint32_t*)(pb + 8);
            pl[3] = *(const uint32_t*)(pb + 8 * TPAD + 8);
            #pragma unroll
            for (int ni = 0; ni < 4; ni++) {
                const int brow = (wn * 32 + ni * 8 + g) * TPAD + k * 16 + c * 2;
                const uint32_t vh0 = *(const uint32_t*)(Vhs + brow);
                const uint32_t vh1 = *(const uint32_t*)(Vhs + brow + 8);
                const uint32_t vl0 = *(const uint32_t*)(Vls + brow);
                const uint32_t vl1 = *(const uint32_t*)(Vls + brow + 8);
                mma16816(o_acc[ni], ph, vh0, vh1);
                mma16816(o_acc[ni], ph, vl0, vl1);
                mma16816(o_acc[ni], pl, vh0, vh1);
            }
        }
        __syncthreads();
    }

    // ---- write unnormalized partials + stats ----
    const size_t rb = (size_t)b * T_ + qb * 64;
    #pragma unroll
    for (int ni = 0; ni < 4; ni++) {
        const int col = wn * 32 + ni * 8 + c * 2;
        float2 v0; v0.x = o_acc[ni][0]; v0.y = o_acc[ni][1];
        float2 v1; v1.x = o_acc[ni][2]; v1.y = o_acc[ni][3];
        *(float2*)(g_opart[sp] + (rb + row_a) * 64 + col) = v0;
        *(float2*)(g_opart[sp] + (rb + row_a + 8) * 64 + col) = v1;
    }
    if (c == 0 && wn == 0) {
        g_m[sp][rb + row_a] = m0;
        g_l[sp][rb + row_a] = l0;
        g_m[sp][rb + row_a + 8] = m1;
        g_l[sp][rb + row_a + 8] = l1;
    }
}

// ---------------------------------------------------------------------------
// Kernel 3: combine split partials.
// ---------------------------------------------------------------------------
__global__ __launch_bounds__(256)
void combine_kernel(float* __restrict__ out) {
    const int t = threadIdx.x;
    const size_t r = (size_t)blockIdx.x * 16 + (t >> 4);
    const int c = (t & 15) * 4;

    float mv[SPLITS], lv[SPLITS];
    float M = NEG_BIG;
    #pragma unroll
    for (int s = 0; s < SPLITS; s++) {
        mv[s] = g_m[s][r];
        lv[s] = g_l[s][r];
        M = fmaxf(M, mv[s]);
    }
    float w[SPLITS], L = 0.0f;
    #pragma unroll
    for (int s = 0; s < SPLITS; s++) {
        w[s] = __expf(mv[s] - M);
        L += lv[s] * w[s];
    }
    float4 acc = make_float4(0.f, 0.f, 0.f, 0.f);
    #pragma unroll
    for (int s = 0; s < SPLITS; s++) {
        const float4 o = *(const float4*)(g_opart[s] + r * 64 + c);
        acc.x += w[s] * o.x; acc.y += w[s] * o.y;
        acc.z += w[s] * o.z; acc.w += w[s] * o.w;
    }
    const float inv = 1.0f / L;
    float4 ov;
    ov.x = acc.x * inv; ov.y = acc.y * inv;
    ov.z = acc.z * inv; ov.w = acc.w * inv;
    *(float4*)(out + r * 64 + c) = ov;
}

// ---------------------------------------------------------------------------
// Launch
// ---------------------------------------------------------------------------
extern "C" void kernel_launch(void* const* d_in, const int* in_sizes, int n_in,
                              void* d_out, int out_size) {
    const float* x  = (const float*)d_in[0];
    const float* Wk = (const float*)d_in[1];
    const float* Wq = (const float*)d_in[2];
    const float* Wv = (const float*)d_in[3];
    float* out = (float*)d_out;

    cudaFuncSetAttribute(proj_mma_kernel,
                         cudaFuncAttributeMaxDynamicSharedMemorySize, PROJ_SMEM);
    cudaFuncSetAttribute(attn_mma_kernel,
                         cudaFuncAttributeMaxDynamicSharedMemorySize, ATTN_SMEM);

    proj_mma_kernel<<<dim3((B_ * T_) / 128, 3), 256, PROJ_SMEM>>>(x, Wq, Wk, Wv);
    attn_mma_kernel<<<dim3(T_ / 64, SPLITS, B_), 256, ATTN_SMEM>>>();
    combine_kernel<<<(B_ * T_) / 16, 256>>>(out);
}